// round 3
// baseline (speedup 1.0000x reference)
#include <cuda_runtime.h>
#include <math.h>

#define NN 50000
#define EE 400000
#define ETOT (EE + NN)

// ---------------- device scratch (no allocations allowed) ----------------
__device__ float g_h1[(size_t)NN * 512];   // layer1 GEMM out
__device__ float g_o1[(size_t)NN * 512];   // layer1 aggregated + elu
__device__ float g_h2[(size_t)NN * 128];
__device__ float g_o2[(size_t)NN * 128];
__device__ float g_h3[(size_t)NN * 8];
__device__ float g_o3[(size_t)NN * 8];
__device__ float g_s[(size_t)NN * 4];
__device__ float g_d[(size_t)NN * 4];
__device__ int   g_deg[NN];
__device__ int   g_off[NN + 1];
__device__ int   g_cur[NN];
__device__ int   g_csrc[ETOT];

// ---------------- CSR build ----------------
__global__ void zero_deg_kernel() {
    int i = blockIdx.x * blockDim.x + threadIdx.x;
    if (i < NN) g_deg[i] = 0;
}

__global__ void hist_deg_kernel(const int* __restrict__ ei) {
    int e = blockIdx.x * blockDim.x + threadIdx.x;
    if (e < ETOT) {
        int dst = (e < EE) ? ei[EE + e] : (e - EE);
        atomicAdd(&g_deg[dst], 1);
    }
}

__global__ void scan_off_kernel() {
    __shared__ int sh[1024];
    __shared__ int carry;
    int tid = threadIdx.x;
    if (tid == 0) { carry = 0; g_off[0] = 0; }
    __syncthreads();
    for (int base = 0; base < NN; base += 1024) {
        int i = base + tid;
        int v = (i < NN) ? g_deg[i] : 0;
        sh[tid] = v;
        __syncthreads();
        for (int st = 1; st < 1024; st <<= 1) {
            int t2 = (tid >= st) ? sh[tid - st] : 0;
            __syncthreads();
            sh[tid] += t2;
            __syncthreads();
        }
        int cb = carry;
        if (i < NN) g_off[i + 1] = cb + sh[tid];
        __syncthreads();
        if (tid == 0) carry = cb + sh[1023];
        __syncthreads();
    }
}

__global__ void init_cur_kernel() {
    int i = blockIdx.x * blockDim.x + threadIdx.x;
    if (i < NN) g_cur[i] = g_off[i];
}

__global__ void scatter_csr_kernel(const int* __restrict__ ei) {
    int e = blockIdx.x * blockDim.x + threadIdx.x;
    if (e < ETOT) {
        int src, dst;
        if (e < EE) { src = ei[e]; dst = ei[EE + e]; }
        else        { src = e - EE; dst = src; }
        int slot = atomicAdd(&g_cur[dst], 1);
        g_csrc[slot] = src;
    }
}

// ---------------- SGEMM: C[M,Ncol] = A[M,K] @ B[Ncol,K]^T ----------------
template<int BM, int BN, int BK, int TM, int TN>
__global__ __launch_bounds__((BM / TM) * (BN / TN))
void sgemm_nt(const float* __restrict__ A, const float* __restrict__ B,
              float* __restrict__ C, int M, int Ncol, int K)
{
    constexpr int THREADS = (BM / TM) * (BN / TN);
    __shared__ float As[BK][BM + 1];
    __shared__ float Bs[BK][BN + 1];
    const int tid = threadIdx.x;
    const int bm = blockIdx.x * BM;
    const int bn = blockIdx.y * BN;
    const int tx = tid % (BN / TN);
    const int ty = tid / (BN / TN);
    float acc[TM][TN];
#pragma unroll
    for (int i = 0; i < TM; i++)
#pragma unroll
        for (int j = 0; j < TN; j++) acc[i][j] = 0.f;

    for (int k0 = 0; k0 < K; k0 += BK) {
#pragma unroll
        for (int i = tid; i < BM * BK; i += THREADS) {
            int r = i / BK, c = i % BK;
            As[c][r] = (bm + r < M) ? A[(size_t)(bm + r) * K + k0 + c] : 0.f;
        }
#pragma unroll
        for (int i = tid; i < BN * BK; i += THREADS) {
            int r = i / BK, c = i % BK;
            Bs[c][r] = (bn + r < Ncol) ? B[(size_t)(bn + r) * K + k0 + c] : 0.f;
        }
        __syncthreads();
#pragma unroll
        for (int kk = 0; kk < BK; kk++) {
            float a[TM], b[TN];
#pragma unroll
            for (int i = 0; i < TM; i++) a[i] = As[kk][ty * TM + i];
#pragma unroll
            for (int j = 0; j < TN; j++) b[j] = Bs[kk][tx * TN + j];
#pragma unroll
            for (int i = 0; i < TM; i++)
#pragma unroll
                for (int j = 0; j < TN; j++) acc[i][j] += a[i] * b[j];
        }
        __syncthreads();
    }
#pragma unroll
    for (int i = 0; i < TM; i++) {
        int row = bm + ty * TM + i;
        if (row < M) {
#pragma unroll
            for (int j = 0; j < TN; j++) {
                int col = bn + tx * TN + j;
                if (col < Ncol) C[(size_t)row * Ncol + col] = acc[i][j];
            }
        }
    }
}

// ---------------- tiny GEMM for layer 3 (Ncol = 8) ----------------
__global__ void gemm_n8(const float* __restrict__ A, const float* __restrict__ W,
                        float* __restrict__ C)
{
    int m = blockIdx.x * blockDim.y + threadIdx.y;
    int j = threadIdx.x;  // 0..7
    if (m >= NN) return;
    const float* a = A + (size_t)m * 128;
    const float* w = W + j * 128;
    float acc = 0.f;
#pragma unroll 8
    for (int k = 0; k < 128; k++) acc += a[k] * w[k];
    C[m * 8 + j] = acc;
}

// ---------------- per-node attention projections s, d ----------------
template<int H, int C>
__global__ void compute_sd(const float* __restrict__ h,
                           const float* __restrict__ as_, const float* __restrict__ ad_,
                           float* __restrict__ s, float* __restrict__ d)
{
    int gw = (blockIdx.x * blockDim.x + threadIdx.x) >> 5;
    int lane = threadIdx.x & 31;
    if (gw >= NN * H) return;
    int n = gw / H, hh = gw % H;
    const float* hp = h + (size_t)n * H * C + (size_t)hh * C;
    float ps = 0.f, pd = 0.f;
    for (int c = lane; c < C; c += 32) {
        float v = hp[c];
        ps += v * as_[hh * C + c];
        pd += v * ad_[hh * C + c];
    }
#pragma unroll
    for (int o = 16; o > 0; o >>= 1) {
        ps += __shfl_down_sync(0xffffffffu, ps, o);
        pd += __shfl_down_sync(0xffffffffu, pd, o);
    }
    if (lane == 0) { s[n * H + hh] = ps; d[n * H + hh] = pd; }
}

// ---------------- GAT aggregate (segment softmax + weighted sum + bias + elu) ----
template<int H, int C, int BLOCK>
__global__ __launch_bounds__(BLOCK)
void gat_aggregate(const float* __restrict__ h, const float* __restrict__ s,
                   const float* __restrict__ dv, const float* __restrict__ bias,
                   float* __restrict__ out)
{
    constexpr int HC = H * C;
    constexpr int TB = 32;                       // edge batch; TB*H <= BLOCK
    constexpr int PER = (HC + BLOCK - 1) / BLOCK;
    __shared__ float red_m[H * BLOCK];
    __shared__ float red_d[H * BLOCK];
    __shared__ float wsh[TB * H];
    __shared__ int   ssh[TB];

    int n = blockIdx.x;
    int tid = threadIdx.x;
    int beg = g_off[n], end = g_off[n + 1];
    int deg = end - beg;

    float dloc[H];
#pragma unroll
    for (int hh = 0; hh < H; hh++) dloc[hh] = dv[n * H + hh];

    // pass 1: per-thread online softmax stats
    float m[H], den[H];
#pragma unroll
    for (int hh = 0; hh < H; hh++) { m[hh] = -1e30f; den[hh] = 0.f; }
    for (int i = tid; i < deg; i += BLOCK) {
        int src = g_csrc[beg + i];
#pragma unroll
        for (int hh = 0; hh < H; hh++) {
            float x = s[src * H + hh] + dloc[hh];
            x = x >= 0.f ? x : 0.2f * x;      // leaky_relu(0.2)
            if (x > m[hh]) {
                den[hh] = den[hh] * __expf(m[hh] - x) + 1.f;
                m[hh] = x;
            } else {
                den[hh] += __expf(x - m[hh]);
            }
        }
    }
#pragma unroll
    for (int hh = 0; hh < H; hh++) { red_m[hh * BLOCK + tid] = m[hh]; red_d[hh * BLOCK + tid] = den[hh]; }
    __syncthreads();
    for (int st = BLOCK / 2; st > 0; st >>= 1) {
        if (tid < st) {
#pragma unroll
            for (int hh = 0; hh < H; hh++) {
                float m1 = red_m[hh * BLOCK + tid], m2 = red_m[hh * BLOCK + tid + st];
                float d1 = red_d[hh * BLOCK + tid], d2 = red_d[hh * BLOCK + tid + st];
                float M = fmaxf(m1, m2);
                red_m[hh * BLOCK + tid] = M;
                red_d[hh * BLOCK + tid] = d1 * __expf(m1 - M) + d2 * __expf(m2 - M);
            }
        }
        __syncthreads();
    }
    float mF[H], dInv[H];
#pragma unroll
    for (int hh = 0; hh < H; hh++) { mF[hh] = red_m[hh * BLOCK]; dInv[hh] = 1.f / red_d[hh * BLOCK]; }

    // pass 2: batched weight compute + gather-accumulate
    float acc[PER];
#pragma unroll
    for (int k = 0; k < PER; k++) acc[k] = 0.f;

    for (int base = 0; base < deg; base += TB) {
        int nb = min(TB, deg - base);
        __syncthreads();
        if (tid < nb * H) {
            int ei = tid / H, hh = tid % H;
            int src = g_csrc[beg + base + ei];
            if (hh == 0) ssh[ei] = src;
            float x = s[src * H + hh] + dloc[hh];
            x = x >= 0.f ? x : 0.2f * x;
            wsh[ei * H + hh] = __expf(x - mF[hh]);   // un-normalized alpha
        }
        __syncthreads();
        for (int ei = 0; ei < nb; ei++) {
            const float* hs = h + (size_t)ssh[ei] * HC;
#pragma unroll
            for (int k = 0; k < PER; k++) {
                int j = tid + k * BLOCK;
                if ((HC % BLOCK == 0) || j < HC) {
                    int hh = j / C;
                    acc[k] += wsh[ei * H + hh] * hs[j];
                }
            }
        }
    }
    // epilogue: normalize, bias, elu
#pragma unroll
    for (int k = 0; k < PER; k++) {
        int j = tid + k * BLOCK;
        if (j < HC) {
            int hh = j / C;
            float v = acc[k] * dInv[hh] + bias[j];
            out[(size_t)n * HC + j] = v > 0.f ? v : expm1f(v);
        }
    }
}

// ---------------- final per-edge MLP ----------------
__global__ void edge_mlp(const float* __restrict__ h3, const int* __restrict__ ei,
                         const float* __restrict__ ea, const float* __restrict__ yr,
                         const float* __restrict__ qt,
                         const float* __restrict__ w1, const float* __restrict__ b1,
                         const float* __restrict__ w2, const float* __restrict__ b2,
                         float* __restrict__ out)
{
    __shared__ float w1s[16 * 19], b1s[16], w2s[16], b2s;
    int t = threadIdx.x;
    for (int i = t; i < 16 * 19; i += blockDim.x) w1s[i] = w1[i];
    if (t < 16) { b1s[t] = b1[t]; w2s[t] = w2[t]; }
    if (t == 0) b2s = b2[0];
    __syncthreads();
    int e = blockIdx.x * blockDim.x + t;
    if (e >= EE) return;
    int sn = ei[e], dn = ei[EE + e];
    float z[19];
#pragma unroll
    for (int i = 0; i < 8; i++) { z[i] = h3[sn * 8 + i]; z[8 + i] = h3[dn * 8 + i]; }
    z[16] = ea[e]; z[17] = yr[e]; z[18] = qt[e];
    float o = b2s;
#pragma unroll
    for (int jj = 0; jj < 16; jj++) {
        float tacc = b1s[jj];
#pragma unroll
        for (int i = 0; i < 19; i++) tacc += w1s[jj * 19 + i] * z[i];
        o += w2s[jj] * fmaxf(tacc, 0.f);
    }
    out[e] = o;
}

// ---------------- launch ----------------
extern "C" void kernel_launch(void* const* d_in, const int* in_sizes, int n_in,
                              void* d_out, int out_size)
{
    const float* x   = (const float*)d_in[0];
    const int*   ei  = (const int*)d_in[1];
    const float* ea  = (const float*)d_in[2];
    const float* yr  = (const float*)d_in[3];
    const float* qt  = (const float*)d_in[4];
    const float* W1  = (const float*)d_in[5];
    const float* a1s = (const float*)d_in[6];
    const float* a1d = (const float*)d_in[7];
    const float* b1  = (const float*)d_in[8];
    const float* W2  = (const float*)d_in[9];
    const float* a2s = (const float*)d_in[10];
    const float* a2d = (const float*)d_in[11];
    const float* b2  = (const float*)d_in[12];
    const float* W3  = (const float*)d_in[13];
    const float* a3s = (const float*)d_in[14];
    const float* a3d = (const float*)d_in[15];
    const float* b3  = (const float*)d_in[16];
    const float* f1w = (const float*)d_in[17];
    const float* f1b = (const float*)d_in[18];
    const float* f2w = (const float*)d_in[19];
    const float* f2b = (const float*)d_in[20];
    float* out = (float*)d_out;

    float *h1, *o1, *h2, *o2, *h3b, *o3, *sb, *db;
    cudaGetSymbolAddress((void**)&h1,  g_h1);
    cudaGetSymbolAddress((void**)&o1,  g_o1);
    cudaGetSymbolAddress((void**)&h2,  g_h2);
    cudaGetSymbolAddress((void**)&o2,  g_o2);
    cudaGetSymbolAddress((void**)&h3b, g_h3);
    cudaGetSymbolAddress((void**)&o3,  g_o3);
    cudaGetSymbolAddress((void**)&sb,  g_s);
    cudaGetSymbolAddress((void**)&db,  g_d);

    // CSR by destination (includes self-loops)
    zero_deg_kernel<<<(NN + 255) / 256, 256>>>();
    hist_deg_kernel<<<(ETOT + 255) / 256, 256>>>(ei);
    scan_off_kernel<<<1, 1024>>>();
    init_cur_kernel<<<(NN + 255) / 256, 256>>>();
    scatter_csr_kernel<<<(ETOT + 255) / 256, 256>>>(ei);

    // ---- layer 1: 128 -> 4 x 128 ----
    {
        dim3 grid((NN + 127) / 128, 512 / 64);
        sgemm_nt<128, 64, 16, 8, 4><<<grid, 256>>>(x, W1, h1, NN, 512, 128);
    }
    compute_sd<4, 128><<<(NN * 4 + 7) / 8, 256>>>(h1, a1s, a1d, sb, db);
    gat_aggregate<4, 128, 128><<<NN, 128>>>(h1, sb, db, b1, o1);

    // ---- layer 2: 512 -> 4 x 32 ----
    {
        dim3 grid((NN + 127) / 128, 128 / 64);
        sgemm_nt<128, 64, 16, 8, 4><<<grid, 256>>>(o1, W2, h2, NN, 128, 512);
    }
    compute_sd<4, 32><<<(NN * 4 + 7) / 8, 256>>>(h2, a2s, a2d, sb, db);
    gat_aggregate<4, 32, 128><<<NN, 128>>>(h2, sb, db, b2, o2);

    // ---- layer 3: 128 -> 1 x 8 ----
    gemm_n8<<<(NN + 31) / 32, dim3(8, 32)>>>(o2, W3, h3b);
    compute_sd<1, 8><<<(NN + 7) / 8, 256>>>(h3b, a3s, a3d, sb, db);
    gat_aggregate<1, 8, 32><<<NN, 32>>>(h3b, sb, db, b3, o3);

    // ---- final edge MLP ----
    edge_mlp<<<(EE + 255) / 256, 256>>>(o3, ei, ea, yr, qt, f1w, f1b, f2w, f2b, out);
}

// round 4
// speedup vs baseline: 2.5012x; 2.5012x over previous
#include <cuda_runtime.h>
#include <math.h>

#define NN 50000
#define EE 400000
#define ETOT (EE + NN)
#define NB_SCAN 49   // ceil(50000/1024)

// ---------------- device scratch (no allocations allowed) ----------------
__device__ float g_h1[(size_t)NN * 512];   // layer1 GEMM out
__device__ float g_o1[(size_t)NN * 512];   // layer1 aggregated + elu
__device__ float g_h2[(size_t)NN * 128];
__device__ float g_o2[(size_t)NN * 128];
__device__ float g_h3[(size_t)NN * 8];
__device__ float g_o3[(size_t)NN * 8];
__device__ float g_s[(size_t)NN * 4];
__device__ float g_d[(size_t)NN * 4];
__device__ int   g_deg[NN];
__device__ int   g_off[NN + 1];
__device__ int   g_cur[NN];
__device__ int   g_csrc[ETOT];
__device__ int   g_bsum[64];
__device__ int   g_bpre[64];

// ---------------- CSR build ----------------
__global__ void zero_deg_kernel() {
    int i = blockIdx.x * blockDim.x + threadIdx.x;
    if (i < NN) g_deg[i] = 0;
}

__global__ void hist_deg_kernel(const int* __restrict__ ei) {
    int e = blockIdx.x * blockDim.x + threadIdx.x;
    if (e < ETOT) {
        int dst = (e < EE) ? ei[EE + e] : (e - EE);
        atomicAdd(&g_deg[dst], 1);
    }
}

// --- fast 3-phase scan of g_deg -> g_off (exclusive) ---
__global__ void scan_part1() {
    __shared__ int ssum[32];
    int tid = threadIdx.x, lane = tid & 31, wid = tid >> 5;
    int i = blockIdx.x * 1024 + tid;
    int v = (i < NN) ? g_deg[i] : 0;
#pragma unroll
    for (int o = 16; o > 0; o >>= 1) v += __shfl_down_sync(0xffffffffu, v, o);
    if (lane == 0) ssum[wid] = v;
    __syncthreads();
    if (wid == 0) {
        int s = ssum[lane];
#pragma unroll
        for (int o = 16; o > 0; o >>= 1) s += __shfl_down_sync(0xffffffffu, s, o);
        if (lane == 0) g_bsum[blockIdx.x] = s;
    }
}

__global__ void scan_part2() {
    int acc = 0;
    for (int b = 0; b < NB_SCAN; b++) { int t = g_bsum[b]; g_bpre[b] = acc; acc += t; }
}

__global__ void scan_part3() {
    __shared__ int wsum[32];
    int tid = threadIdx.x, lane = tid & 31, wid = tid >> 5;
    int b = blockIdx.x;
    int i = b * 1024 + tid;
    int v = (i < NN) ? g_deg[i] : 0;
    int incl = v;
#pragma unroll
    for (int o = 1; o < 32; o <<= 1) {
        int t = __shfl_up_sync(0xffffffffu, incl, o);
        if (lane >= o) incl += t;
    }
    if (lane == 31) wsum[wid] = incl;
    __syncthreads();
    if (wid == 0) {
        int s = wsum[lane];
#pragma unroll
        for (int o = 1; o < 32; o <<= 1) {
            int t = __shfl_up_sync(0xffffffffu, s, o);
            if (lane >= o) s += t;
        }
        wsum[lane] = s;
    }
    __syncthreads();
    int pre = (wid > 0) ? wsum[wid - 1] : 0;
    if (i < NN) g_off[i + 1] = g_bpre[b] + pre + incl;
    if (b == 0 && tid == 0) g_off[0] = 0;
}

__global__ void init_cur_kernel() {
    int i = blockIdx.x * blockDim.x + threadIdx.x;
    if (i < NN) g_cur[i] = g_off[i];
}

__global__ void scatter_csr_kernel(const int* __restrict__ ei) {
    int e = blockIdx.x * blockDim.x + threadIdx.x;
    if (e < ETOT) {
        int src, dst;
        if (e < EE) { src = ei[e]; dst = ei[EE + e]; }
        else        { src = e - EE; dst = src; }
        int slot = atomicAdd(&g_cur[dst], 1);
        g_csrc[slot] = src;
    }
}

// ---------------- TF32 tensor-core GEMM: C[M,Ncol] = A[M,K] @ B[Ncol,K]^T ----
// BM=128, BN=64, BK=32; 256 threads, 4x2 warp grid, 32x32 warp tiles.
// Requires: Ncol % 64 == 0, K % 32 == 0. M arbitrary (row guards).
__device__ __forceinline__ unsigned f2tf32(float f) {
    unsigned r;
    asm("cvt.rna.tf32.f32 %0, %1;" : "=r"(r) : "f"(f));
    return r;
}

__device__ __forceinline__ void mma_tf32(float c[4], const unsigned a[4], const unsigned b[2]) {
    asm volatile(
        "mma.sync.aligned.m16n8k8.row.col.f32.tf32.tf32.f32 "
        "{%0,%1,%2,%3}, {%4,%5,%6,%7}, {%8,%9}, {%0,%1,%2,%3};"
        : "+f"(c[0]), "+f"(c[1]), "+f"(c[2]), "+f"(c[3])
        : "r"(a[0]), "r"(a[1]), "r"(a[2]), "r"(a[3]), "r"(b[0]), "r"(b[1]));
}

__global__ __launch_bounds__(256)
void tf32_gemm_nt(const float* __restrict__ A, const float* __restrict__ B,
                  float* __restrict__ C, int M, int Ncol, int K)
{
    constexpr int BM = 128, BN = 64, BK = 32, LDS_ = BK + 4; // 36-word rows
    __shared__ unsigned As[BM * LDS_];
    __shared__ unsigned Bs[BN * LDS_];
    const int tid = threadIdx.x;
    const int lane = tid & 31, wid = tid >> 5;
    const int wm = wid >> 1, wn = wid & 1;        // 4 x 2 warps
    const int gr = lane >> 2, tg = lane & 3;
    const int bm = blockIdx.x * BM, bn = blockIdx.y * BN;

    float acc[2][4][4];
#pragma unroll
    for (int mt = 0; mt < 2; mt++)
#pragma unroll
        for (int nt = 0; nt < 4; nt++)
#pragma unroll
            for (int j = 0; j < 4; j++) acc[mt][nt][j] = 0.f;

    for (int k0 = 0; k0 < K; k0 += BK) {
        // A: 128x32 floats = 1024 float4, 4 per thread
#pragma unroll
        for (int it = 0; it < 4; it++) {
            int i = tid + it * 256;
            int r = i >> 3, c4 = i & 7;
            int row = bm + r;
            unsigned u0 = 0, u1 = 0, u2 = 0, u3 = 0;
            if (row < M) {
                float4 v = *(const float4*)(A + (size_t)row * K + k0 + c4 * 4);
                u0 = f2tf32(v.x); u1 = f2tf32(v.y); u2 = f2tf32(v.z); u3 = f2tf32(v.w);
            }
            uint4 p; p.x = u0; p.y = u1; p.z = u2; p.w = u3;
            *(uint4*)&As[r * LDS_ + c4 * 4] = p;
        }
        // B: 64x32 floats = 512 float4, 2 per thread
#pragma unroll
        for (int it = 0; it < 2; it++) {
            int i = tid + it * 256;
            int r = i >> 3, c4 = i & 7;
            float4 v = *(const float4*)(B + (size_t)(bn + r) * K + k0 + c4 * 4);
            uint4 p;
            p.x = f2tf32(v.x); p.y = f2tf32(v.y); p.z = f2tf32(v.z); p.w = f2tf32(v.w);
            *(uint4*)&Bs[r * LDS_ + c4 * 4] = p;
        }
        __syncthreads();

#pragma unroll
        for (int ks = 0; ks < BK; ks += 8) {
            unsigned af[2][4], bf[4][2];
#pragma unroll
            for (int mt = 0; mt < 2; mt++) {
                int row = wm * 32 + mt * 16 + gr;
                af[mt][0] = As[row * LDS_ + ks + tg];
                af[mt][1] = As[(row + 8) * LDS_ + ks + tg];
                af[mt][2] = As[row * LDS_ + ks + tg + 4];
                af[mt][3] = As[(row + 8) * LDS_ + ks + tg + 4];
            }
#pragma unroll
            for (int nt = 0; nt < 4; nt++) {
                int col = wn * 32 + nt * 8 + gr;
                bf[nt][0] = Bs[col * LDS_ + ks + tg];
                bf[nt][1] = Bs[col * LDS_ + ks + tg + 4];
            }
#pragma unroll
            for (int mt = 0; mt < 2; mt++)
#pragma unroll
                for (int nt = 0; nt < 4; nt++)
                    mma_tf32(acc[mt][nt], af[mt], bf[nt]);
        }
        __syncthreads();
    }

    // epilogue
#pragma unroll
    for (int mt = 0; mt < 2; mt++) {
        int r0 = bm + wm * 32 + mt * 16 + gr;
#pragma unroll
        for (int nt = 0; nt < 4; nt++) {
            int c = bn + wn * 32 + nt * 8 + tg * 2;
            if (r0 < M) {
                float2 v; v.x = acc[mt][nt][0]; v.y = acc[mt][nt][1];
                *(float2*)&C[(size_t)r0 * Ncol + c] = v;
            }
            if (r0 + 8 < M) {
                float2 v; v.x = acc[mt][nt][2]; v.y = acc[mt][nt][3];
                *(float2*)&C[(size_t)(r0 + 8) * Ncol + c] = v;
            }
        }
    }
}

// ---------------- tiny GEMM for layer 3 (Ncol = 8) ----------------
__global__ void gemm_n8(const float* __restrict__ A, const float* __restrict__ W,
                        float* __restrict__ C)
{
    int m = blockIdx.x * blockDim.y + threadIdx.y;
    int j = threadIdx.x;  // 0..7
    if (m >= NN) return;
    const float* a = A + (size_t)m * 128;
    const float* w = W + j * 128;
    float acc = 0.f;
#pragma unroll 8
    for (int k = 0; k < 128; k++) acc += a[k] * w[k];
    C[m * 8 + j] = acc;
}

// ---------------- per-node attention projections s, d ----------------
template<int H, int C>
__global__ void compute_sd(const float* __restrict__ h,
                           const float* __restrict__ as_, const float* __restrict__ ad_,
                           float* __restrict__ s, float* __restrict__ d)
{
    int gw = (blockIdx.x * blockDim.x + threadIdx.x) >> 5;
    int lane = threadIdx.x & 31;
    if (gw >= NN * H) return;
    int n = gw / H, hh = gw % H;
    const float* hp = h + (size_t)n * H * C + (size_t)hh * C;
    float ps = 0.f, pd = 0.f;
    for (int c = lane; c < C; c += 32) {
        float v = hp[c];
        ps += v * as_[hh * C + c];
        pd += v * ad_[hh * C + c];
    }
#pragma unroll
    for (int o = 16; o > 0; o >>= 1) {
        ps += __shfl_down_sync(0xffffffffu, ps, o);
        pd += __shfl_down_sync(0xffffffffu, pd, o);
    }
    if (lane == 0) { s[n * H + hh] = ps; d[n * H + hh] = pd; }
}

// ---------------- GAT aggregate (segment softmax + weighted sum + bias + elu) ----
template<int H, int C, int BLOCK>
__global__ __launch_bounds__(BLOCK)
void gat_aggregate(const float* __restrict__ h, const float* __restrict__ s,
                   const float* __restrict__ dv, const float* __restrict__ bias,
                   float* __restrict__ out)
{
    constexpr int HC = H * C;
    constexpr int TB = 32;                       // edge batch; TB*H <= BLOCK
    constexpr int PER = (HC + BLOCK - 1) / BLOCK;
    __shared__ float red_m[H * BLOCK];
    __shared__ float red_d[H * BLOCK];
    __shared__ float wsh[TB * H];
    __shared__ int   ssh[TB];

    int n = blockIdx.x;
    int tid = threadIdx.x;
    int beg = g_off[n], end = g_off[n + 1];
    int deg = end - beg;

    float dloc[H];
#pragma unroll
    for (int hh = 0; hh < H; hh++) dloc[hh] = dv[n * H + hh];

    // pass 1: per-thread online softmax stats
    float m[H], den[H];
#pragma unroll
    for (int hh = 0; hh < H; hh++) { m[hh] = -1e30f; den[hh] = 0.f; }
    for (int i = tid; i < deg; i += BLOCK) {
        int src = g_csrc[beg + i];
#pragma unroll
        for (int hh = 0; hh < H; hh++) {
            float x = s[src * H + hh] + dloc[hh];
            x = x >= 0.f ? x : 0.2f * x;      // leaky_relu(0.2)
            if (x > m[hh]) {
                den[hh] = den[hh] * __expf(m[hh] - x) + 1.f;
                m[hh] = x;
            } else {
                den[hh] += __expf(x - m[hh]);
            }
        }
    }
#pragma unroll
    for (int hh = 0; hh < H; hh++) { red_m[hh * BLOCK + tid] = m[hh]; red_d[hh * BLOCK + tid] = den[hh]; }
    __syncthreads();
    for (int st = BLOCK / 2; st > 0; st >>= 1) {
        if (tid < st) {
#pragma unroll
            for (int hh = 0; hh < H; hh++) {
                float m1 = red_m[hh * BLOCK + tid], m2 = red_m[hh * BLOCK + tid + st];
                float d1 = red_d[hh * BLOCK + tid], d2 = red_d[hh * BLOCK + tid + st];
                float M = fmaxf(m1, m2);
                red_m[hh * BLOCK + tid] = M;
                red_d[hh * BLOCK + tid] = d1 * __expf(m1 - M) + d2 * __expf(m2 - M);
            }
        }
        __syncthreads();
    }
    float mF[H], dInv[H];
#pragma unroll
    for (int hh = 0; hh < H; hh++) { mF[hh] = red_m[hh * BLOCK]; dInv[hh] = 1.f / red_d[hh * BLOCK]; }

    // pass 2: batched weight compute + gather-accumulate
    float acc[PER];
#pragma unroll
    for (int k = 0; k < PER; k++) acc[k] = 0.f;

    for (int base = 0; base < deg; base += TB) {
        int nb = min(TB, deg - base);
        __syncthreads();
        if (tid < nb * H) {
            int ei = tid / H, hh = tid % H;
            int src = g_csrc[beg + base + ei];
            if (hh == 0) ssh[ei] = src;
            float x = s[src * H + hh] + dloc[hh];
            x = x >= 0.f ? x : 0.2f * x;
            wsh[ei * H + hh] = __expf(x - mF[hh]);   // un-normalized alpha
        }
        __syncthreads();
        for (int ei = 0; ei < nb; ei++) {
            const float* hs = h + (size_t)ssh[ei] * HC;
#pragma unroll
            for (int k = 0; k < PER; k++) {
                int j = tid + k * BLOCK;
                if ((HC % BLOCK == 0) || j < HC) {
                    int hh = j / C;
                    acc[k] += wsh[ei * H + hh] * hs[j];
                }
            }
        }
    }
    // epilogue: normalize, bias, elu
#pragma unroll
    for (int k = 0; k < PER; k++) {
        int j = tid + k * BLOCK;
        if (j < HC) {
            int hh = j / C;
            float v = acc[k] * dInv[hh] + bias[j];
            out[(size_t)n * HC + j] = v > 0.f ? v : expm1f(v);
        }
    }
}

// ---------------- final per-edge MLP ----------------
__global__ void edge_mlp(const float* __restrict__ h3, const int* __restrict__ ei,
                         const float* __restrict__ ea, const float* __restrict__ yr,
                         const float* __restrict__ qt,
                         const float* __restrict__ w1, const float* __restrict__ b1,
                         const float* __restrict__ w2, const float* __restrict__ b2,
                         float* __restrict__ out)
{
    __shared__ float w1s[16 * 19], b1s[16], w2s[16], b2s;
    int t = threadIdx.x;
    for (int i = t; i < 16 * 19; i += blockDim.x) w1s[i] = w1[i];
    if (t < 16) { b1s[t] = b1[t]; w2s[t] = w2[t]; }
    if (t == 0) b2s = b2[0];
    __syncthreads();
    int e = blockIdx.x * blockDim.x + t;
    if (e >= EE) return;
    int sn = ei[e], dn = ei[EE + e];
    float z[19];
#pragma unroll
    for (int i = 0; i < 8; i++) { z[i] = h3[sn * 8 + i]; z[8 + i] = h3[dn * 8 + i]; }
    z[16] = ea[e]; z[17] = yr[e]; z[18] = qt[e];
    float o = b2s;
#pragma unroll
    for (int jj = 0; jj < 16; jj++) {
        float tacc = b1s[jj];
#pragma unroll
        for (int i = 0; i < 19; i++) tacc += w1s[jj * 19 + i] * z[i];
        o += w2s[jj] * fmaxf(tacc, 0.f);
    }
    out[e] = o;
}

// ---------------- launch ----------------
extern "C" void kernel_launch(void* const* d_in, const int* in_sizes, int n_in,
                              void* d_out, int out_size)
{
    const float* x   = (const float*)d_in[0];
    const int*   ei  = (const int*)d_in[1];
    const float* ea  = (const float*)d_in[2];
    const float* yr  = (const float*)d_in[3];
    const float* qt  = (const float*)d_in[4];
    const float* W1  = (const float*)d_in[5];
    const float* a1s = (const float*)d_in[6];
    const float* a1d = (const float*)d_in[7];
    const float* b1  = (const float*)d_in[8];
    const float* W2  = (const float*)d_in[9];
    const float* a2s = (const float*)d_in[10];
    const float* a2d = (const float*)d_in[11];
    const float* b2  = (const float*)d_in[12];
    const float* W3  = (const float*)d_in[13];
    const float* a3s = (const float*)d_in[14];
    const float* a3d = (const float*)d_in[15];
    const float* b3  = (const float*)d_in[16];
    const float* f1w = (const float*)d_in[17];
    const float* f1b = (const float*)d_in[18];
    const float* f2w = (const float*)d_in[19];
    const float* f2b = (const float*)d_in[20];
    float* out = (float*)d_out;

    float *h1, *o1, *h2, *o2, *h3b, *o3, *sb, *db;
    cudaGetSymbolAddress((void**)&h1,  g_h1);
    cudaGetSymbolAddress((void**)&o1,  g_o1);
    cudaGetSymbolAddress((void**)&h2,  g_h2);
    cudaGetSymbolAddress((void**)&o2,  g_o2);
    cudaGetSymbolAddress((void**)&h3b, g_h3);
    cudaGetSymbolAddress((void**)&o3,  g_o3);
    cudaGetSymbolAddress((void**)&sb,  g_s);
    cudaGetSymbolAddress((void**)&db,  g_d);

    // CSR by destination (includes self-loops)
    zero_deg_kernel<<<(NN + 255) / 256, 256>>>();
    hist_deg_kernel<<<(ETOT + 255) / 256, 256>>>(ei);
    scan_part1<<<NB_SCAN, 1024>>>();
    scan_part2<<<1, 1>>>();
    scan_part3<<<NB_SCAN, 1024>>>();
    init_cur_kernel<<<(NN + 255) / 256, 256>>>();
    scatter_csr_kernel<<<(ETOT + 255) / 256, 256>>>(ei);

    // ---- layer 1: 128 -> 4 x 128 (tf32 tensor cores) ----
    {
        dim3 grid((NN + 127) / 128, 512 / 64);
        tf32_gemm_nt<<<grid, 256>>>(x, W1, h1, NN, 512, 128);
    }
    compute_sd<4, 128><<<(NN * 4 + 7) / 8, 256>>>(h1, a1s, a1d, sb, db);
    gat_aggregate<4, 128, 128><<<NN, 128>>>(h1, sb, db, b1, o1);

    // ---- layer 2: 512 -> 4 x 32 (tf32 tensor cores) ----
    {
        dim3 grid((NN + 127) / 128, 128 / 64);
        tf32_gemm_nt<<<grid, 256>>>(o1, W2, h2, NN, 128, 512);
    }
    compute_sd<4, 32><<<(NN * 4 + 7) / 8, 256>>>(h2, a2s, a2d, sb, db);
    gat_aggregate<4, 32, 128><<<NN, 128>>>(h2, sb, db, b2, o2);

    // ---- layer 3: 128 -> 1 x 8 ----
    gemm_n8<<<(NN + 31) / 32, dim3(8, 32)>>>(o2, W3, h3b);
    compute_sd<1, 8><<<(NN + 7) / 8, 256>>>(h3b, a3s, a3d, sb, db);
    gat_aggregate<1, 8, 32><<<NN, 32>>>(h3b, sb, db, b3, o3);

    // ---- final edge MLP ----
    edge_mlp<<<(EE + 255) / 256, 256>>>(o3, ei, ea, yr, qt, f1w, f1b, f2w, f2b, out);
}